// round 15
// baseline (speedup 1.0000x reference)
#include <cuda_runtime.h>
#include <cuda_fp16.h>
#include <math.h>
#include <cstdint>

#define CDIM 160
#define HW 12544
#define WIMG 112
#define NIMG 32
#define NTHREADS 256
#define TILE_PX 64
#define TILES_PER_CTA 7
#define NBLOCKS 896          // 896 * 7 * 64px = 32*12544 px

#define PA 168      // A smem pitch (fp16) -> conflict-free ldmatrix
#define PB 72       // B smem pitch (fp16) -> conflict-free ldmatrix.trans
#define PD 72       // staging pitch (halves), aliases dead B buffer
#define BSIZE (CDIM * PB * 2)   // 23040 bytes, one B tile

// shared memory byte offsets
#define SM_BIAS  0
#define SM_A     2048                       // 160*168*2 = 53760
#define SM_B0    (SM_A + CDIM * PA * 2)     // 55808
#define SM_B1    (SM_B0 + BSIZE)            // 78848
#define SM_TOTAL (SM_B1 + BSIZE)            // 101888 (2 CTAs/SM)

// xh = fp16(gelu(bn(x))), channel-major — written by pre-pass
__device__ __half g_xh[(size_t)NIMG * CDIM * HW + 16];
// PRE-SHIFTED intermediate: yt[c][p] = (shifted y)[c][p], channel-major fp16.
__device__ __half g_yt[(size_t)NIMG * CDIM * HW + 16];

// ---------------------------------------------------------------------------
__device__ __forceinline__ uint32_t smem_u32(const void* p) {
    uint32_t a;
    asm("{ .reg .u64 t; cvta.to.shared.u64 t, %1; cvt.u32.u64 %0, t; }" : "=r"(a) : "l"(p));
    return a;
}
__device__ __forceinline__ void ldsm_x4(uint32_t* r, uint32_t addr) {
    asm volatile("ldmatrix.sync.aligned.m8n8.x4.shared.b16 {%0,%1,%2,%3}, [%4];"
        : "=r"(r[0]), "=r"(r[1]), "=r"(r[2]), "=r"(r[3]) : "r"(addr));
}
__device__ __forceinline__ void ldsm_x4t(uint32_t* r, uint32_t addr) {
    asm volatile("ldmatrix.sync.aligned.m8n8.x4.trans.shared.b16 {%0,%1,%2,%3}, [%4];"
        : "=r"(r[0]), "=r"(r[1]), "=r"(r[2]), "=r"(r[3]) : "r"(addr));
}
__device__ __forceinline__ void mma16816(float* d, const uint32_t* a, const uint32_t* b) {
    asm volatile("mma.sync.aligned.m16n8k16.row.col.f32.f16.f16.f32 "
        "{%0,%1,%2,%3}, {%4,%5,%6,%7}, {%8,%9}, {%0,%1,%2,%3};"
        : "+f"(d[0]), "+f"(d[1]), "+f"(d[2]), "+f"(d[3])
        : "r"(a[0]), "r"(a[1]), "r"(a[2]), "r"(a[3]), "r"(b[0]), "r"(b[1]));
}
__device__ __forceinline__ void cp_async16(uint32_t saddr, const void* gptr) {
    asm volatile("cp.async.cg.shared.global [%0], [%1], 16;" :: "r"(saddr), "l"(gptr));
}
#define CP_COMMIT() asm volatile("cp.async.commit_group;" ::: "memory")
#define CP_WAIT0()  asm volatile("cp.async.wait_group 0;" ::: "memory")

// fast exact-GELU: erf via Abramowitz-Stegun 7.1.26, |abs err| <= 1.5e-7
__device__ __forceinline__ float fast_gelu(float h) {
    const float x = h * 0.70710678118654752f;
    const float ax = fabsf(x);
    const float t = __fdividef(1.0f, fmaf(0.3275911f, ax, 1.0f));
    float p = fmaf(t, 1.061405429f, -1.453152027f);
    p = fmaf(t, p, 1.421413741f);
    p = fmaf(t, p, -0.284496736f);
    p = fmaf(t, p, 0.254829592f);
    p *= t;
    const float e = __expf(-ax * ax);
    const float erf_abs = fmaf(-p, e, 1.0f);
    const float erf_v = copysignf(erf_abs, x);
    return 0.5f * h * (1.0f + erf_v);
}

// ---------------------------------------------------------------------------
// Pre-pass: xh = fp16(gelu(bn(x))), pure stream, float4 in / 8B out
// ---------------------------------------------------------------------------
#define PRE_BLOCKS 2368
__global__ __launch_bounds__(256) void bn_gelu_pre(
    const float* __restrict__ x,
    const float* __restrict__ gamma, const float* __restrict__ beta,
    const float* __restrict__ rmean, const float* __restrict__ rvar) {
    __shared__ float sc[CDIM], sh[CDIM];
    const int tid = threadIdx.x;
    if (tid < CDIM) {
        float s = gamma[tid] * rsqrtf(rvar[tid] + 1e-5f);
        sc[tid] = s;
        sh[tid] = beta[tid] - rmean[tid] * s;
    }
    __syncthreads();

    const int total4 = NIMG * CDIM * (HW / 4);   // 16,056,320 float4s
    for (int i = blockIdx.x * 256 + tid; i < total4; i += PRE_BLOCKS * 256) {
        const int cidx = i / (HW / 4);           // global channel index
        const int c = cidx - (cidx / CDIM) * CDIM;
        const float4 v = __ldg((const float4*)x + i);
        const float s = sc[c], b = sh[c];
        float g0 = fast_gelu(fmaf(v.x, s, b));
        float g1 = fast_gelu(fmaf(v.y, s, b));
        float g2 = fast_gelu(fmaf(v.z, s, b));
        float g3 = fast_gelu(fmaf(v.w, s, b));
        __half2 o2[2];
        o2[0] = __floats2half2_rn(g0, g1);
        o2[1] = __floats2half2_rn(g2, g3);
        *(float2*)(g_xh + (size_t)i * 4) = *(float2*)o2;
    }
}

// ---------------------------------------------------------------------------
// Kernel 1': yt = scatter_shift( W_cat @ xh + b_cat )  — gemm2-clone prep,
// R13 span-scatter epilogue.
// ---------------------------------------------------------------------------
__global__ __launch_bounds__(NTHREADS, 2) void gemm1_mma(
    const float* __restrict__ Wt, const float* __restrict__ bt,
    const float* __restrict__ Wb, const float* __restrict__ bb,
    const float* __restrict__ Wr, const float* __restrict__ br,
    const float* __restrict__ Wl, const float* __restrict__ bl,
    const float* __restrict__ Wc, const float* __restrict__ bc) {
    extern __shared__ char smem[];
    const uint32_t sb = smem_u32(smem);
    const int tid = threadIdx.x;
    const int wid = tid >> 5, lane = tid & 31;
    float* bias_s = (float*)(smem + SM_BIAS);
    __half* Aw = (__half*)(smem + SM_A);

    const float* Wseg[5] = {Wt, Wb, Wr, Wl, Wc};
    for (int idx = tid; idx < CDIM * CDIM; idx += NTHREADS) {
        int m = idx / CDIM;
        int k = idx - m * CDIM;
        Aw[m * PA + k] = __float2half_rn(Wseg[m >> 5][(m & 31) * CDIM + k]);
    }
    if (tid < CDIM) {
        const float* bp[5] = {bt, bb, br, bl, bc};
        bias_s[tid] = bp[tid >> 5][tid & 31];
    }
    __syncthreads();

    const int slot = tid & 7;
    const int chbase = (tid >> 3) * 5;
    const int wm = wid >> 2, wn = wid & 3;
    const int tr = lane >> 2, tc = 2 * (lane & 3);

    const uint32_t a_lane = (uint32_t)((wm * 80 + (lane & 15)) * (PA * 2) + (lane >> 4) * 16);
    const uint32_t b_lane = (uint32_t)((lane & 15) * (PB * 2) + (wn * 16 + (lane >> 4) * 8) * 2);
    const uint32_t Ab = sb + SM_A + a_lane;

    auto issue_cp = [&](int tile, uint32_t bufoff) {
        const int b = (tile * TILE_PX) / HW;
        const int p0 = tile * TILE_PX - b * HW;
        const __half* xb = g_xh + (size_t)b * CDIM * HW + p0 + slot * 8;
#pragma unroll
        for (int j = 0; j < 5; ++j)
            cp_async16(sb + bufoff + (uint32_t)(((chbase + j) * PB + slot * 8) * 2),
                       xb + (size_t)(chbase + j) * HW);
        CP_COMMIT();
    };

    issue_cp(blockIdx.x * TILES_PER_CTA, SM_B0);
    CP_WAIT0();
    __syncthreads();

    for (int t = 0; t < TILES_PER_CTA; ++t) {
        const int tile = blockIdx.x * TILES_PER_CTA + t;
        const int b = (tile * TILE_PX) / HW;
        const int p0 = tile * TILE_PX - b * HW;
        const uint32_t curbuf = (t & 1) ? SM_B1 : SM_B0;
        const uint32_t nxtoff = (t & 1) ? SM_B0 : SM_B1;

        if (t + 1 < TILES_PER_CTA) issue_cp(tile + 1, nxtoff);  // async under MMA

        float acc[5][2][4] = {};
        const uint32_t Bb = sb + curbuf + b_lane;
#pragma unroll
        for (int kk = 0; kk < 10; ++kk) {
            const int k0 = kk * 16;
            uint32_t a[5][4];
#pragma unroll
            for (int mi = 0; mi < 5; ++mi)
                ldsm_x4(a[mi], Ab + mi * 16 * (PA * 2) + k0 * 2);
            uint32_t bfr[4];
            ldsm_x4t(bfr, Bb + k0 * (PB * 2));
#pragma unroll
            for (int mi = 0; mi < 5; ++mi) {
                mma16816(acc[mi][0], a[mi], bfr);
                mma16816(acc[mi][1], a[mi], bfr + 2);
            }
        }
        __syncthreads();                    // all curbuf reads done

        // stage D (+bias -> fp16) into the dead current B buffer
        {
            __half* Dst = (__half*)(smem + curbuf);
#pragma unroll
            for (int mi = 0; mi < 5; ++mi) {
#pragma unroll
                for (int row = 0; row < 2; ++row) {
                    const int r = wm * 80 + mi * 16 + row * 8 + tr;
                    const float bia = bias_s[r];
                    *(__half2*)(Dst + r * PD + wn * 16 + tc) =
                        __floats2half2_rn(acc[mi][0][row * 2 + 0] + bia,
                                          acc[mi][0][row * 2 + 1] + bia);
                    *(__half2*)(Dst + r * PD + wn * 16 + 8 + tc) =
                        __floats2half2_rn(acc[mi][1][row * 2 + 0] + bia,
                                          acc[mi][1][row * 2 + 1] + bia);
                }
            }
        }
        __syncthreads();                    // staging complete

        // write-out by 8-px spans: 1280 spans, 5 per thread
        {
            const __half* Dst = (const __half*)(smem + curbuf);
            __half* yb = g_yt + (size_t)b * CDIM * HW;
#pragma unroll
            for (int i = 0; i < 5; ++i) {
                const int item = i * NTHREADS + tid;
                const int ch = item >> 3;
                const int sp = item & 7;
                const int q = p0 + sp * 8;
                const int h = q / WIMG;
                const int w0 = q - h * WIMG;
                const int seg = ch >> 5;
                const uint4 v4 = *(const uint4*)(Dst + ch * PD + sp * 8);
                __half* base = yb + (size_t)ch * HW;
                if (seg == 0) {                     // shift up: y[q] -> yt[q-112]
                    if (h > 0) *(uint4*)(base + q - WIMG) = v4;
                    else       *(uint4*)(base + q + (WIMG - 1) * WIMG) = make_uint4(0, 0, 0, 0);
                } else if (seg == 1) {              // shift down: -> yt[q+112]
                    if (h < WIMG - 1) *(uint4*)(base + q + WIMG) = v4;
                    else              *(uint4*)(base + q - (WIMG - 1) * WIMG) = make_uint4(0, 0, 0, 0);
                } else if (seg == 2) {              // yt[p]=y[p-1]
                    const uint32_t pa = (v4.x >> 16) | (v4.y << 16);
                    const uint32_t pb = (v4.y >> 16) | (v4.z << 16);
                    const uint32_t pc = (v4.z >> 16) | (v4.w << 16);
                    *(uint16_t*)(base + q + 1) = (uint16_t)(v4.x & 0xFFFFu);
                    *(uint32_t*)(base + q + 2) = pa;
                    *(uint32_t*)(base + q + 4) = pb;
                    *(uint32_t*)(base + q + 6) = pc;
                    if (w0 < 104) *(uint16_t*)(base + q + 8) = (uint16_t)(v4.w >> 16);
                    if (w0 == 0)  *(uint16_t*)(base + q) = 0;
                } else if (seg == 3) {              // yt[p]=y[p+1]
                    const uint32_t pa = (v4.x >> 16) | (v4.y << 16);
                    const uint32_t pb = (v4.y >> 16) | (v4.z << 16);
                    const uint32_t pc = (v4.z >> 16) | (v4.w << 16);
                    if (w0 > 0) *(uint16_t*)(base + q - 1) = (uint16_t)(v4.x & 0xFFFFu);
                    *(uint32_t*)(base + q)     = pa;
                    *(uint32_t*)(base + q + 2) = pb;
                    *(uint32_t*)(base + q + 4) = pc;
                    *(uint16_t*)(base + q + 6) = (uint16_t)(v4.w >> 16);
                    if (w0 == 104) *(uint16_t*)(base + q + 7) = 0;
                } else {                            // center
                    *(uint4*)(base + q) = v4;
                }
            }
        }

        CP_WAIT0();                         // next tile's cp.async landed
        __syncthreads();                    // tile end
    }
}

// ---------------------------------------------------------------------------
// Kernel 2: out = W_fuse @ yt + b_fuse   (cp.async 16B prefetch for B)
// ---------------------------------------------------------------------------
__global__ __launch_bounds__(NTHREADS, 2) void gemm2_mma(
    const float* __restrict__ Wf, const float* __restrict__ bf,
    float* __restrict__ out) {
    extern __shared__ char smem[];
    const uint32_t sb = smem_u32(smem);
    const int tid = threadIdx.x;
    const int wid = tid >> 5, lane = tid & 31;
    float* bias_s = (float*)(smem + SM_BIAS);
    __half* Aw = (__half*)(smem + SM_A);

    for (int idx = tid; idx < CDIM * CDIM; idx += NTHREADS) {
        int m = idx / CDIM;
        int k = idx - m * CDIM;
        Aw[m * PA + k] = __float2half_rn(Wf[m * CDIM + k]);
    }
    if (tid < CDIM) bias_s[tid] = bf[tid];
    __syncthreads();

    const int slot = tid & 7;
    const int chbase = (tid >> 3) * 5;
    const int wm = wid >> 2, wn = wid & 3;
    const int tr = lane >> 2, tc = 2 * (lane & 3);

    const uint32_t a_lane = (uint32_t)((wm * 80 + (lane & 15)) * (PA * 2) + (lane >> 4) * 16);
    const uint32_t b_lane = (uint32_t)((lane & 15) * (PB * 2) + (wn * 16 + (lane >> 4) * 8) * 2);
    const uint32_t Ab = sb + SM_A + a_lane;

    auto issue_cp = [&](int tile, uint32_t bufoff) {
        const int b = (tile * TILE_PX) / HW;
        const int p0 = tile * TILE_PX - b * HW;
        const __half* yb = g_yt + (size_t)b * CDIM * HW + p0 + slot * 8;
#pragma unroll
        for (int j = 0; j < 5; ++j)
            cp_async16(sb + bufoff + (uint32_t)(((chbase + j) * PB + slot * 8) * 2),
                       yb + (size_t)(chbase + j) * HW);
        CP_COMMIT();
    };

    issue_cp(blockIdx.x * TILES_PER_CTA, SM_B0);
    CP_WAIT0();
    __syncthreads();

    for (int t = 0; t < TILES_PER_CTA; ++t) {
        const int tile = blockIdx.x * TILES_PER_CTA + t;
        const int b = (tile * TILE_PX) / HW;
        const int p0 = tile * TILE_PX - b * HW;
        const uint32_t curbuf = (t & 1) ? SM_B1 : SM_B0;
        const uint32_t nxtoff = (t & 1) ? SM_B0 : SM_B1;

        if (t + 1 < TILES_PER_CTA) issue_cp(tile + 1, nxtoff);  // async under MMA

        float acc[5][2][4] = {};
        const uint32_t Bb = sb + curbuf + b_lane;
#pragma unroll
        for (int kk = 0; kk < 10; ++kk) {
            const int k0 = kk * 16;
            uint32_t a[5][4];
#pragma unroll
            for (int mi = 0; mi < 5; ++mi)
                ldsm_x4(a[mi], Ab + mi * 16 * (PA * 2) + k0 * 2);
            uint32_t bfr[4];
            ldsm_x4t(bfr, Bb + k0 * (PB * 2));
#pragma unroll
            for (int mi = 0; mi < 5; ++mi) {
                mma16816(acc[mi][0], a[mi], bfr);
                mma16816(acc[mi][1], a[mi], bfr + 2);
            }
        }

        CP_WAIT0();                                  // next tile landed

        float* ob = out + (size_t)b * CDIM * HW + p0;
#pragma unroll
        for (int mi = 0; mi < 5; ++mi) {
            const int r0 = wm * 80 + mi * 16 + tr;
            const float bia0 = bias_s[r0];
            const float bia1 = bias_s[r0 + 8];
#pragma unroll
            for (int ni = 0; ni < 2; ++ni) {
                const int c = wn * 16 + ni * 8 + tc;
                *(float2*)(ob + (size_t)r0 * HW + c) =
                    make_float2(acc[mi][ni][0] + bia0, acc[mi][ni][1] + bia0);
                *(float2*)(ob + (size_t)(r0 + 8) * HW + c) =
                    make_float2(acc[mi][ni][2] + bia1, acc[mi][ni][3] + bia1);
            }
        }
        __syncthreads();
    }
}

// ---------------------------------------------------------------------------
extern "C" void kernel_launch(void* const* d_in, const int* in_sizes, int n_in,
                              void* d_out, int out_size) {
    const float* x     = (const float*)d_in[0];
    const float* gamma = (const float*)d_in[1];
    const float* beta  = (const float*)d_in[2];
    const float* rmean = (const float*)d_in[3];
    const float* rvar  = (const float*)d_in[4];
    const float* Wt = (const float*)d_in[5];  const float* bt = (const float*)d_in[6];
    const float* Wb = (const float*)d_in[7];  const float* bb = (const float*)d_in[8];
    const float* Wr = (const float*)d_in[9];  const float* br = (const float*)d_in[10];
    const float* Wl = (const float*)d_in[11]; const float* bl = (const float*)d_in[12];
    const float* Wc = (const float*)d_in[13]; const float* bc = (const float*)d_in[14];
    const float* Wf = (const float*)d_in[15]; const float* bf = (const float*)d_in[16];

    cudaFuncSetAttribute(gemm1_mma, cudaFuncAttributeMaxDynamicSharedMemorySize, SM_TOTAL);
    cudaFuncSetAttribute(gemm2_mma, cudaFuncAttributeMaxDynamicSharedMemorySize, SM_TOTAL);

    bn_gelu_pre<<<PRE_BLOCKS, 256>>>(x, gamma, beta, rmean, rvar);
    gemm1_mma<<<NBLOCKS, NTHREADS, SM_TOTAL>>>(Wt, bt, Wb, bb, Wr, br, Wl, bl, Wc, bc);
    gemm2_mma<<<NBLOCKS, NTHREADS, SM_TOTAL>>>(Wf, bf, (float*)d_out);
}